// round 13
// baseline (speedup 1.0000x reference)
#include <cuda_runtime.h>
#include <cuda_fp16.h>

#define QF 64
#define PTS_PER_WARP 348   // multiple of 12; 5748 warps -> 719 blocks <= 740 (5/SM) = ONE wave

__global__ void perslay_zero_kernel(float4* __restrict__ out, int n4) {
    int i = blockIdx.x * blockDim.x + threadIdx.x;
    if (i < n4) out[i] = make_float4(0.f, 0.f, 0.f, 0.f);
}

__device__ __forceinline__ float ex2f(float x) {
    float r;
    asm("ex2.approx.f32 %0, %1;" : "=f"(r) : "f"(x));
    return r;
}

// ex2 on both halves in ONE MUFU op.
__device__ __forceinline__ __half2 h2ex2(__half2 v) {
    unsigned a = *reinterpret_cast<unsigned*>(&v);
    unsigned r;
    asm("ex2.approx.f16x2 %0, %1;" : "=r"(r) : "r"(a));
    return *reinterpret_cast<__half2*>(&r);
}

__global__ __launch_bounds__(256, 5) void perslay_kernel(
    const float2* __restrict__ xy,
    const int*    __restrict__ seg,
    const float*  __restrict__ sp,
    const float*  __restrict__ isg,
    float*        __restrict__ out,
    int n)
{
    const int warp_id = blockIdx.x * (blockDim.x >> 5) + (threadIdx.x >> 5);
    const int lane    = threadIdx.x & 31;
    const int start   = warp_id * PTS_PER_WARP;
    if (start >= n) return;
    const int end = min(start + PTS_PER_WARP, n);

    const int q0 = 2 * lane;
    const int q1 = q0 + 1;

    // sqrt(log2 e) folded into sigma scale so a bare ex2 replaces exp.
    const float SL  = 1.2011224087864498f;
    const float px0 = sp[q0],      px1 = sp[q1];
    const float py0 = sp[QF + q0], py1 = sp[QF + q1];
    const float ax0 = isg[q0]      * SL, ax1 = isg[q1]      * SL;
    const float ay0 = isg[QF + q0] * SL, ay1 = isg[QF + q1] * SL;

    // t = A x^2 + B x + Ay y^2 + By y + C  (log2 units). fp16 path computes
    // t' = t - C; the 2^C factor is applied at flush in fp32.
    const float A0  = -ax0 * ax0,       A1  = -ax1 * ax1;
    const float Ay0 = -ay0 * ay0,       Ay1 = -ay1 * ay1;
    const float B0  = -2.f * A0  * px0, B1  = -2.f * A1  * px1;
    const float By0 = -2.f * Ay0 * py0, By1 = -2.f * Ay1 * py1;
    const float C0  = A0 * px0 * px0 + Ay0 * py0 * py0;
    const float C1  = A1 * px1 * px1 + Ay1 * py1 * py1;
    const float E0  = ex2f(C0);   // 2^C, fp32-exact scale applied at flush
    const float E1  = ex2f(C1);

    const __half2 A2  = __floats2half2_rn(A0,  A1);   // lo->q0, hi->q1
    const __half2 B2  = __floats2half2_rn(B0,  B1);
    const __half2 Ay2 = __floats2half2_rn(Ay0, Ay1);
    const __half2 By2 = __floats2half2_rn(By0, By1);
    const __half2 H2Z = __floats2half2_rn(0.f, 0.f);

    const float4* __restrict__ cp   = (const float4*)(xy + start);  // 2 pts / float4
    const int*    __restrict__ segp = seg + start;
    float*        __restrict__ outP = out + q0;

    // Two rotating half2 accumulators: <=6 adds each per 12-pt chunk
    // (tighter than the validated 8-add bound) + fp32 carries.
    __half2 haA = H2Z, haB = H2Z;
    float acc0 = 0.f, acc1 = 0.f;
    int cur = segp[0];

    // Per point, both q's at once:
    //   u = A*x+B; w = Ay*y+By; t' = x*u + y*w; acc += 2^t'
    #define PBODY(X, Y, HACC) do {                                         \
        const __half2 xx_ = __float2half2_rn(X);                           \
        const __half2 yy_ = __float2half2_rn(Y);                           \
        const __half2 u_  = __hfma2(xx_, A2, B2);                          \
        const __half2 w_  = __hfma2(yy_, Ay2, By2);                        \
        const __half2 t_  = __hfma2(yy_, w_, __hmul2(xx_, u_));            \
        HACC = __hadd2(HACC, h2ex2(t_));                                   \
    } while (0)
    #define POINT_A(X, Y) PBODY(X, Y, haA)
    #define POINT_B(X, Y) PBODY(X, Y, haB)

    // Drain half2 accumulators into fp32 (per chunk + before any flush).
    #define DRAIN() do {                                                   \
        const float2 fa_ = __half22float2(__hadd2(haA, haB));              \
        acc0 += fa_.x; acc1 += fa_.y;                                      \
        haA = H2Z; haB = H2Z;                                              \
    } while (0)

    #define FLUSH() do {                                                   \
        DRAIN();                                                           \
        atomicAdd(&outP[cur * QF],     acc0 * E0);                         \
        atomicAdd(&outP[cur * QF + 1], acc1 * E1);                         \
        acc0 = 0.f; acc1 = 0.f;                                            \
    } while (0)

    // Cold-arm helper: per-point segment tracking for one float4 (2 points).
    #define COLD2(V, SPTR, I) do {                                         \
        int sv_;                                                           \
        sv_ = (SPTR)[(I)];     if (sv_ != cur) { FLUSH(); cur = sv_; }     \
        POINT_A(V.x, V.y);                                                 \
        sv_ = (SPTR)[(I) + 1]; if (sv_ != cur) { FLUSH(); cur = sv_; }     \
        POINT_B(V.z, V.w);                                                 \
    } while (0)

    int p = start;
    // 12-point chunks: 6 front-batched coord LDG.128 + 1 scalar seg LDG
    // (MLP_p1=7, half of R12) at 10 warps/SMSP -> correlated L1tex-queue
    // stalls are both shorter and covered by more eligible warps.
    // Sorted invariant: seg[i] >= cur for i >= p, so seg[p+11]==cur <=> the
    // whole chunk belongs to 'cur'.
    for (; p + 12 <= end; p += 12, cp += 6, segp += 12) {
        const float4 cA = cp[0], cB = cp[1], cC = cp[2];
        const float4 cD = cp[3], cE = cp[4], cF = cp[5];
        const int slast = segp[11];
        if (slast == cur) {
            POINT_A(cA.x, cA.y);  POINT_B(cA.z, cA.w);
            POINT_A(cB.x, cB.y);  POINT_B(cB.z, cB.w);
            POINT_A(cC.x, cC.y);  POINT_B(cC.z, cC.w);
            POINT_A(cD.x, cD.y);  POINT_B(cD.z, cD.w);
            POINT_A(cE.x, cE.y);  POINT_B(cE.z, cE.w);
            POINT_A(cF.x, cF.y);  POINT_B(cF.z, cF.w);
        } else {
            // Cold arm (~2.5% of chunks): per-point segment tracking.
            COLD2(cA, segp, 0);   COLD2(cB, segp, 2);
            COLD2(cC, segp, 4);   COLD2(cD, segp, 6);
            COLD2(cE, segp, 8);   COLD2(cF, segp, 10);
        }
        DRAIN();   // bound fp16 accumulation length to one chunk
    }
    for (; p < end; ++p, ++segp) {   // tail (< 12 points)
        const float2 c  = xy[p];
        const int    sv = segp[0];
        if (sv != cur) { FLUSH(); cur = sv; }
        POINT_A(c.x, c.y);
    }
    FLUSH();

    #undef COLD2
    #undef FLUSH
    #undef DRAIN
    #undef POINT_A
    #undef POINT_B
    #undef PBODY
}

extern "C" void kernel_launch(void* const* d_in, const int* in_sizes, int n_in,
                              void* d_out, int out_size) {
    const float2* xy  = (const float2*)d_in[0];
    const int*    seg = (const int*)   d_in[1];
    const float*  sp  = (const float*) d_in[2];
    const float*  isg = (const float*) d_in[3];
    float*        out = (float*)d_out;

    const int n = in_sizes[0] / 2;   // input is [N,2] float32

    const int n4 = out_size >> 2;    // 4096*64 / 4
    perslay_zero_kernel<<<(n4 + 255) / 256, 256>>>((float4*)out, n4);

    const int num_warps = (n + PTS_PER_WARP - 1) / PTS_PER_WARP;
    const int blocks    = (num_warps + 7) / 8;   // 8 warps / block
    perslay_kernel<<<blocks, 256>>>(xy, seg, sp, isg, out, n);
}